// round 6
// baseline (speedup 1.0000x reference)
#include <cuda_runtime.h>

#define NMAX 100000
#define EMAX 600000
#define TPB  512
#define NPW  4            // nodes per warp per iteration
#define WARPS_PER_CTA (TPB/32)

// ---- scratch (device globals: no allocation allowed) ----
__device__ int  g_deg[NMAX];
__device__ int  g_cursor[NMAX];
__device__ int  g_rowptr[NMAX + 1];
__device__ int  g_blocksum[256];
__device__ int  g_blockoff[256];
__device__ int2 g_csr[EMAX];      // {src j, edge id e} grouped by destination i

// ---------------- CSR build ----------------

__global__ void k_zero(int N) {
    int i = blockIdx.x * blockDim.x + threadIdx.x;
    if (i < N) { g_deg[i] = 0; g_cursor[i] = 0; }
}

// edge_index is int32 (JAX x64 disabled): layout [ i[0..E) , j[0..E) ]
__global__ void k_hist(const int* __restrict__ ei, int E) {
    int e = blockIdx.x * blockDim.x + threadIdx.x;
    if (e < E) atomicAdd(&g_deg[ei[e]], 1);
}

__global__ __launch_bounds__(1024) void k_scan1(int N) {
    __shared__ int s[1024];
    int t = threadIdx.x;
    int i = blockIdx.x * 1024 + t;
    int v = (i < N) ? g_deg[i] : 0;
    s[t] = v;
    __syncthreads();
    for (int off = 1; off < 1024; off <<= 1) {
        int a = (t >= off) ? s[t - off] : 0;
        __syncthreads();
        s[t] += a;
        __syncthreads();
    }
    if (i < N) g_rowptr[i] = s[t] - v;   // exclusive
    if (t == 1023) g_blocksum[blockIdx.x] = s[1023];
}

__global__ void k_scan2(int nblk) {
    if (threadIdx.x == 0 && blockIdx.x == 0) {
        int acc = 0;
        for (int b = 0; b < nblk; b++) { g_blockoff[b] = acc; acc += g_blocksum[b]; }
    }
}

__global__ void k_scan3(int N, int E) {
    int i = blockIdx.x * blockDim.x + threadIdx.x;
    if (i < N) g_rowptr[i] += g_blockoff[i >> 10];
    if (i == 0) g_rowptr[N] = E;
}

__global__ void k_fill(const int* __restrict__ ei, int E) {
    int e = blockIdx.x * blockDim.x + threadIdx.x;
    if (e < E) {
        int i = ei[e];
        int j = ei[E + e];
        int p = g_rowptr[i] + atomicAdd(&g_cursor[i], 1);
        g_csr[p] = make_int2(j, e);
    }
}

// ---------------- fused node kernel ----------------
// agg = gather(x[j]) + (gather_sum(edge_attr)) @ We + deg*be
// h   = (1+eps)*x + agg
// out = LN( relu(h@W1+b1) @ W2 + b2 ) * gamma + beta

__global__ __launch_bounds__(TPB, 1) void k_node(
    const float* __restrict__ x,  const float* __restrict__ ea,
    const float* __restrict__ We, const float* __restrict__ be,
    const float* __restrict__ W1, const float* __restrict__ b1,
    const float* __restrict__ W2, const float* __restrict__ b2,
    const float* __restrict__ epsp,
    const float* __restrict__ gamma, const float* __restrict__ beta,
    float* __restrict__ out, int N)
{
    extern __shared__ float sm[];
    float* W1s = sm;                 // 16384 f
    float* W2s = sm + 16384;         // 16384 f
    float* Wes = sm + 32768;         // 4096 f
    float* hb  = sm + 36864;         // WARPS_PER_CTA * NPW*128 f

    // cooperative weight staging
    {
        const float4* s1 = (const float4*)W1;
        const float4* s2 = (const float4*)W2;
        const float4* se = (const float4*)We;
        float4* d1 = (float4*)W1s; float4* d2 = (float4*)W2s; float4* de = (float4*)Wes;
        for (int i = threadIdx.x; i < 4096; i += TPB) { d1[i] = s1[i]; d2[i] = s2[i]; }
        for (int i = threadIdx.x; i < 1024; i += TPB) de[i] = se[i];
    }
    __syncthreads();

    const int lane = threadIdx.x & 31;
    const int w    = threadIdx.x >> 5;
    float*  hw  = hb + w * (NPW * 128);
    float4* hw4 = (float4*)hw;

    const float4* x4 = (const float4*)x;
    const float eps1 = 1.0f + epsp[0];
    const float4 be4 = ((const float4*)be)[lane];
    const float4 b14 = ((const float4*)b1)[lane];
    const float4 b24 = ((const float4*)b2)[lane];
    const float4 g4  = ((const float4*)gamma)[lane];
    const float4 bt4 = ((const float4*)beta)[lane];

    const float4* W1s4 = (const float4*)W1s;
    const float4* W2s4 = (const float4*)W2s;
    const float4* Wes4 = (const float4*)Wes;

    const int warpsTotal = gridDim.x * WARPS_PER_CTA;

    for (int base = (blockIdx.x * WARPS_PER_CTA + w) * NPW; base < N;
         base += warpsTotal * NPW)
    {
        float4 hv[NPW];
        float  ae[NPW];

        // ---- gather + aggregate (per node) ----
        #pragma unroll
        for (int n = 0; n < NPW; n++) {
            int node = base + n;
            float4 acc = make_float4(0.f, 0.f, 0.f, 0.f);
            float  a   = 0.f;
            if (node < N) {                       // warp-uniform branch
                int sP = g_rowptr[node];
                int eP = g_rowptr[node + 1];
                int dg = eP - sP;
                for (int p0 = sP; p0 < eP; p0 += 32) {
                    int cnt = min(32, eP - p0);
                    int2 je = (lane < cnt) ? g_csr[p0 + lane] : make_int2(0, 0);
                    for (int m = 0; m < cnt; m++) {
                        int jm = __shfl_sync(0xffffffffu, je.x, m);
                        int em = __shfl_sync(0xffffffffu, je.y, m);
                        float4 xv = x4[jm * 32 + lane];
                        acc.x += xv.x; acc.y += xv.y; acc.z += xv.z; acc.w += xv.w;
                        a += ea[em * 32 + lane];
                    }
                }
                float4 xi = x4[node * 32 + lane];
                float  df = (float)dg;
                acc.x = fmaf(eps1, xi.x, acc.x) + df * be4.x;
                acc.y = fmaf(eps1, xi.y, acc.y) + df * be4.y;
                acc.z = fmaf(eps1, xi.z, acc.z) + df * be4.z;
                acc.w = fmaf(eps1, xi.w, acc.w) + df * be4.w;
            }
            hv[n] = acc;
            ae[n] = a;
        }

        // ---- edge-feature transform: hv += (sum edge_attr) @ We ----
        #pragma unroll 4
        for (int k = 0; k < 32; k++) {
            float4 wv = Wes4[k * 32 + lane];
            #pragma unroll
            for (int n = 0; n < NPW; n++) {
                float a = __shfl_sync(0xffffffffu, ae[n], k);
                hv[n].x = fmaf(a, wv.x, hv[n].x);
                hv[n].y = fmaf(a, wv.y, hv[n].y);
                hv[n].z = fmaf(a, wv.z, hv[n].z);
                hv[n].w = fmaf(a, wv.w, hv[n].w);
            }
        }

        // ---- stage h ----
        __syncwarp();
        #pragma unroll
        for (int n = 0; n < NPW; n++) hw4[n * 32 + lane] = hv[n];
        __syncwarp();

        // ---- layer 1: u = h @ W1 + b1 ----
        float4 u[NPW];
        #pragma unroll
        for (int n = 0; n < NPW; n++) u[n] = b14;
        #pragma unroll 4
        for (int k = 0; k < 128; k++) {
            float4 wv = W1s4[k * 32 + lane];
            #pragma unroll
            for (int n = 0; n < NPW; n++) {
                float hk = hw[n * 128 + k];
                u[n].x = fmaf(hk, wv.x, u[n].x);
                u[n].y = fmaf(hk, wv.y, u[n].y);
                u[n].z = fmaf(hk, wv.z, u[n].z);
                u[n].w = fmaf(hk, wv.w, u[n].w);
            }
        }

        // ---- relu, restage ----
        __syncwarp();
        #pragma unroll
        for (int n = 0; n < NPW; n++) {
            u[n].x = fmaxf(u[n].x, 0.f); u[n].y = fmaxf(u[n].y, 0.f);
            u[n].z = fmaxf(u[n].z, 0.f); u[n].w = fmaxf(u[n].w, 0.f);
            hw4[n * 32 + lane] = u[n];
        }
        __syncwarp();

        // ---- layer 2: o = relu(u) @ W2 + b2 ----
        float4 o[NPW];
        #pragma unroll
        for (int n = 0; n < NPW; n++) o[n] = b24;
        #pragma unroll 4
        for (int k = 0; k < 128; k++) {
            float4 wv = W2s4[k * 32 + lane];
            #pragma unroll
            for (int n = 0; n < NPW; n++) {
                float rk = hw[n * 128 + k];
                o[n].x = fmaf(rk, wv.x, o[n].x);
                o[n].y = fmaf(rk, wv.y, o[n].y);
                o[n].z = fmaf(rk, wv.z, o[n].z);
                o[n].w = fmaf(rk, wv.w, o[n].w);
            }
        }

        // ---- LayerNorm + store ----
        #pragma unroll
        for (int n = 0; n < NPW; n++) {
            int node = base + n;
            if (node >= N) break;                 // warp-uniform
            float4 ov = o[n];
            float s1 = ov.x + ov.y + ov.z + ov.w;
            float s2 = ov.x*ov.x + ov.y*ov.y + ov.z*ov.z + ov.w*ov.w;
            #pragma unroll
            for (int off = 16; off >= 1; off >>= 1) {
                s1 += __shfl_xor_sync(0xffffffffu, s1, off);
                s2 += __shfl_xor_sync(0xffffffffu, s2, off);
            }
            float mu  = s1 * 0.0078125f;
            float var = s2 * 0.0078125f - mu * mu;
            float rs  = rsqrtf(var + 1e-5f);
            float4 r;
            r.x = (ov.x - mu) * rs * g4.x + bt4.x;
            r.y = (ov.y - mu) * rs * g4.y + bt4.y;
            r.z = (ov.z - mu) * rs * g4.z + bt4.z;
            r.w = (ov.w - mu) * rs * g4.w + bt4.w;
            ((float4*)out)[node * 32 + lane] = r;
        }
    }
}

// ---------------- launch ----------------

extern "C" void kernel_launch(void* const* d_in, const int* in_sizes, int n_in,
                              void* d_out, int out_size)
{
    const float* x     = (const float*)d_in[0];
    const int*   ei    = (const int*)d_in[1];     // int32! (JAX x64 disabled)
    const float* ea    = (const float*)d_in[2];
    const float* We    = (const float*)d_in[3];
    const float* be    = (const float*)d_in[4];
    const float* W1    = (const float*)d_in[5];
    const float* b1    = (const float*)d_in[6];
    const float* W2    = (const float*)d_in[7];
    const float* b2    = (const float*)d_in[8];
    const float* eps   = (const float*)d_in[9];
    const float* gamma = (const float*)d_in[10];
    const float* beta  = (const float*)d_in[11];
    float* out = (float*)d_out;

    int N = in_sizes[0] / 128;
    int E = in_sizes[1] / 2;
    if (N > NMAX) N = NMAX;
    if (E > EMAX) E = EMAX;

    k_zero<<<(N + 511) / 512, 512>>>(N);
    k_hist<<<(E + 511) / 512, 512>>>(ei, E);
    int nblk = (N + 1023) / 1024;
    k_scan1<<<nblk, 1024>>>(N);
    k_scan2<<<1, 32>>>(nblk);
    k_scan3<<<(N + 1023) / 1024, 1024>>>(N, E);
    k_fill<<<(E + 511) / 512, 512>>>(ei, E);

    size_t smem = (size_t)(16384 + 16384 + 4096 + WARPS_PER_CTA * NPW * 128) * sizeof(float);
    cudaFuncSetAttribute(k_node, cudaFuncAttributeMaxDynamicSharedMemorySize, (int)smem);
    k_node<<<152, TPB, smem>>>(x, ea, We, be, W1, b1, W2, b2, eps, gamma, beta, out, N);
}